// round 4
// baseline (speedup 1.0000x reference)
#include <cuda_runtime.h>
#include <stdint.h>

// TBE pooled embedding forward via TMA bulk gather.
// weights: [T, E, D] fp32; indices: [T*B*L] int32; offsets: [T*B+1] int32
// out: [B, T*D] fp32, pooled bag (t, b) -> out[b, t*D : (t+1)*D]
//
// One warp per bag. Lanes 0..chunk-1 each issue a 512B cp.async.bulk G->S of
// their row into a per-warp smem slab; one mbarrier tracks the bytes; the
// warp then reduces the slab with conflict-free LDS.128. This moves the
// gather off the LSU/L1tex wavefront queue (cap ~248 wf/SM, which limited
// in-flight bytes to ~4.7MB chip-wide) onto the TMA path.

#define T_TABLES 16
#define E_ROWS   100000
#define D_DIM    128
#define B_BAGS   4096
#define LCHUNK   20
#define WARPS    8
#define ROW_BYTES 512
#define SLAB_BYTES (LCHUNK * ROW_BYTES)              // 10240
#define SMEM_BYTES (128 + WARPS * SLAB_BYTES)        // 82048

__device__ __forceinline__ uint32_t smem_u32(const void* p) {
    return (uint32_t)__cvta_generic_to_shared(p);
}

__global__ __launch_bounds__(WARPS * 32)
void tbe_tma_kernel(const float* __restrict__ weights,
                    const int* __restrict__ indices,
                    const int* __restrict__ offsets,
                    float* __restrict__ out) {
    extern __shared__ char smem[];
    const int wid  = threadIdx.x >> 5;
    const int lane = threadIdx.x & 31;
    const int bag  = blockIdx.x * WARPS + wid;

    const int t = bag / B_BAGS;   // bags are table-major
    const int b = bag % B_BAGS;

    const uint32_t mbar   = smem_u32(smem + wid * 16);
    char* const slab      = smem + 128 + wid * SLAB_BYTES;
    const uint32_t slab_s = smem_u32(slab);

    if (lane == 0) {
        asm volatile("mbarrier.init.shared.b64 [%0], %1;"
                     :: "r"(mbar), "r"(1) : "memory");
    }
    // Make barrier init visible to the async proxy before TMA uses it.
    asm volatile("fence.proxy.async.shared::cta;" ::: "memory");
    __syncwarp();

    const int start = offsets[bag];
    const int end   = offsets[bag + 1];

    const char* const tbl =
        reinterpret_cast<const char*>(weights + (size_t)t * E_ROWS * D_DIM);

    float4 acc = make_float4(0.f, 0.f, 0.f, 0.f);
    int phase = 0;

    for (int cs = start; cs < end; cs += LCHUNK) {
        const int clen = min(LCHUNK, end - cs);

        if (lane == 0) {
            asm volatile("mbarrier.arrive.expect_tx.shared.b64 _, [%0], %1;"
                         :: "r"(mbar), "r"(clen * ROW_BYTES) : "memory");
        }
        __syncwarp();

        if (lane < clen) {
            const int idx = indices[cs + lane];
            const char* g = tbl + (size_t)idx * ROW_BYTES;
            asm volatile(
                "cp.async.bulk.shared::cluster.global.mbarrier::complete_tx::bytes "
                "[%0], [%1], %2, [%3];"
                :: "r"(slab_s + lane * ROW_BYTES), "l"(g),
                   "r"(ROW_BYTES), "r"(mbar)
                : "memory");
        }

        // All lanes wait for the chunk's bytes to land.
        asm volatile(
            "{\n\t"
            ".reg .pred P;\n\t"
            "WAIT_%=:\n\t"
            "mbarrier.try_wait.parity.acquire.cta.shared::cta.b64 P, [%0], %1, 0x989680;\n\t"
            "@P bra WAIT_DONE_%=;\n\t"
            "bra WAIT_%=;\n\t"
            "WAIT_DONE_%=:\n\t"
            "}"
            :: "r"(mbar), "r"(phase) : "memory");
        phase ^= 1;

        // Reduce the slab: row k, lane owns float4 slot `lane` (conflict-free).
        const float4* rows = reinterpret_cast<const float4*>(slab);
        #pragma unroll
        for (int k = 0; k < LCHUNK; k++) {
            if (k < clen) {
                const float4 v = rows[k * (ROW_BYTES / 16) + lane];
                acc.x += v.x; acc.y += v.y; acc.z += v.z; acc.w += v.w;
            }
        }
        __syncwarp();  // slab reuse safety for next chunk
    }

    float4* const o =
        reinterpret_cast<float4*>(out + (size_t)b * (T_TABLES * D_DIM) + t * D_DIM);
    o[lane] = acc;
}

extern "C" void kernel_launch(void* const* d_in, const int* in_sizes, int n_in,
                              void* d_out, int out_size) {
    const float* weights = (const float*)d_in[0];
    const int*   indices = (const int*)d_in[1];
    const int*   offsets = (const int*)d_in[2];
    float*       out     = (float*)d_out;

    cudaFuncSetAttribute(tbe_tma_kernel,
                         cudaFuncAttributeMaxDynamicSharedMemorySize, SMEM_BYTES);

    const int num_bags = T_TABLES * B_BAGS;        // 65536
    const int blocks   = num_bags / WARPS;          // 8192
    tbe_tma_kernel<<<blocks, WARPS * 32, SMEM_BYTES>>>(weights, indices, offsets, out);
}

// round 5
// speedup vs baseline: 1.1084x; 1.1084x over previous
#include <cuda_runtime.h>
#include <stdint.h>

// TBE pooled embedding forward — hybrid LDG + TMA gather.
// weights: [T, E, D] fp32; indices: [T*B*L] int32; offsets: [T*B+1] int32
// out: [B, T*D] fp32, pooled bag (t, b) -> out[b, t*D : (t+1)*D]
//
// Per bag (one warp): 12 rows gathered via LDG.128 (fills the LSU/L1tex
// wavefront queue, ~32KB in-flight/SM) and 8 rows via cp.async.bulk G->S
// (in-flight bytes ride the async/TMA queue instead). The TMA latency is
// overlapped behind the LDG loads; then the warp reduces the smem slab.

#define T_TABLES 16
#define E_ROWS   100000
#define D_DIM    128
#define B_BAGS   4096
#define WARPS    8
#define ROW_BYTES 512
#define LDG_ROWS 12
#define TMA_ROWS 8
#define SLAB_BYTES (TMA_ROWS * ROW_BYTES)            // 4096
#define SMEM_BYTES (128 + WARPS * SLAB_BYTES)        // 32896

__device__ __forceinline__ uint32_t smem_u32(const void* p) {
    return (uint32_t)__cvta_generic_to_shared(p);
}

__device__ __forceinline__ float4 ldcg_f4(const float4* p) {
    float4 v;
    asm volatile("ld.global.cg.v4.f32 {%0,%1,%2,%3}, [%4];"
                 : "=f"(v.x), "=f"(v.y), "=f"(v.z), "=f"(v.w) : "l"(p));
    return v;
}

__device__ __forceinline__ void acc_add(float4& a, const float4 v) {
    a.x += v.x; a.y += v.y; a.z += v.z; a.w += v.w;
}

__global__ __launch_bounds__(WARPS * 32, 6)
void tbe_hybrid_kernel(const float* __restrict__ weights,
                       const int* __restrict__ indices,
                       const int* __restrict__ offsets,
                       float* __restrict__ out) {
    extern __shared__ char smem[];
    const int wid  = threadIdx.x >> 5;
    const int lane = threadIdx.x & 31;
    const int bag  = blockIdx.x * WARPS + wid;

    const int t = bag / B_BAGS;   // bags are table-major
    const int b = bag % B_BAGS;

    const uint32_t mbar   = smem_u32(smem + wid * 16);
    char* const slab      = smem + 128 + wid * SLAB_BYTES;
    const uint32_t slab_s = smem_u32(slab);

    if (lane == 0) {
        asm volatile("mbarrier.init.shared.b64 [%0], %1;"
                     :: "r"(mbar), "r"(1) : "memory");
    }
    asm volatile("fence.proxy.async.shared::cta;" ::: "memory");
    __syncwarp();

    const int start = offsets[bag];
    const int end   = offsets[bag + 1];
    const int n     = end - start;

    const float4* __restrict__ tbl =
        reinterpret_cast<const float4*>(weights + (size_t)t * E_ROWS * D_DIM);
    const char* const tblc = reinterpret_cast<const char*>(tbl);

    float4 a0 = make_float4(0.f, 0.f, 0.f, 0.f);
    float4 a1 = make_float4(0.f, 0.f, 0.f, 0.f);
    float4 a2 = make_float4(0.f, 0.f, 0.f, 0.f);
    float4 a3 = make_float4(0.f, 0.f, 0.f, 0.f);

    if (n == (LDG_ROWS + TMA_ROWS) && ((start & 3) == 0)) {
        // ---- 1) launch TMA gathers for the last 8 rows ----
        if (lane == 0) {
            asm volatile("mbarrier.arrive.expect_tx.shared.b64 _, [%0], %1;"
                         :: "r"(mbar), "r"(TMA_ROWS * ROW_BYTES) : "memory");
        }
        __syncwarp();
        if (lane < TMA_ROWS) {
            const int idx = indices[start + LDG_ROWS + lane];
            const char* g = tblc + (size_t)idx * ROW_BYTES;
            asm volatile(
                "cp.async.bulk.shared::cluster.global.mbarrier::complete_tx::bytes "
                "[%0], [%1], %2, [%3];"
                :: "r"(slab_s + lane * ROW_BYTES), "l"(g),
                   "r"(ROW_BYTES), "r"(mbar)
                : "memory");
        }

        // ---- 2) LDG gathers for the first 12 rows (overlaps TMA latency) ----
        const int4* __restrict__ ip = reinterpret_cast<const int4*>(indices + start);
        const int4 q0 = ip[0];
        const int4 q1 = ip[1];
        const int4 q2 = ip[2];
        float4 v[LDG_ROWS];
        v[0]  = ldcg_f4(tbl + (size_t)q0.x * (D_DIM / 4) + lane);
        v[1]  = ldcg_f4(tbl + (size_t)q0.y * (D_DIM / 4) + lane);
        v[2]  = ldcg_f4(tbl + (size_t)q0.z * (D_DIM / 4) + lane);
        v[3]  = ldcg_f4(tbl + (size_t)q0.w * (D_DIM / 4) + lane);
        v[4]  = ldcg_f4(tbl + (size_t)q1.x * (D_DIM / 4) + lane);
        v[5]  = ldcg_f4(tbl + (size_t)q1.y * (D_DIM / 4) + lane);
        v[6]  = ldcg_f4(tbl + (size_t)q1.z * (D_DIM / 4) + lane);
        v[7]  = ldcg_f4(tbl + (size_t)q1.w * (D_DIM / 4) + lane);
        v[8]  = ldcg_f4(tbl + (size_t)q2.x * (D_DIM / 4) + lane);
        v[9]  = ldcg_f4(tbl + (size_t)q2.y * (D_DIM / 4) + lane);
        v[10] = ldcg_f4(tbl + (size_t)q2.z * (D_DIM / 4) + lane);
        v[11] = ldcg_f4(tbl + (size_t)q2.w * (D_DIM / 4) + lane);
        #pragma unroll
        for (int k = 0; k < LDG_ROWS; k += 4) {
            acc_add(a0, v[k + 0]);
            acc_add(a1, v[k + 1]);
            acc_add(a2, v[k + 2]);
            acc_add(a3, v[k + 3]);
        }

        // ---- 3) wait for TMA bytes and reduce the slab ----
        asm volatile(
            "{\n\t"
            ".reg .pred P;\n\t"
            "WAIT_%=:\n\t"
            "mbarrier.try_wait.parity.acquire.cta.shared::cta.b64 P, [%0], 0, 0x989680;\n\t"
            "@P bra WAIT_DONE_%=;\n\t"
            "bra WAIT_%=;\n\t"
            "WAIT_DONE_%=:\n\t"
            "}"
            :: "r"(mbar) : "memory");

        const float4* rows = reinterpret_cast<const float4*>(slab);
        #pragma unroll
        for (int k = 0; k < TMA_ROWS; k += 4) {
            acc_add(a0, rows[(k + 0) * (ROW_BYTES / 16) + lane]);
            acc_add(a1, rows[(k + 1) * (ROW_BYTES / 16) + lane]);
            acc_add(a2, rows[(k + 2) * (ROW_BYTES / 16) + lane]);
            acc_add(a3, rows[(k + 3) * (ROW_BYTES / 16) + lane]);
        }
    } else {
        // Generic ragged fallback: pure LDG.
        int j = start;
        const int n4 = start + (n & ~3);
        #pragma unroll 1
        for (; j < n4; j += 4) {
            const int i0 = indices[j + 0];
            const int i1 = indices[j + 1];
            const int i2 = indices[j + 2];
            const int i3 = indices[j + 3];
            acc_add(a0, ldcg_f4(tbl + (size_t)i0 * (D_DIM / 4) + lane));
            acc_add(a1, ldcg_f4(tbl + (size_t)i1 * (D_DIM / 4) + lane));
            acc_add(a2, ldcg_f4(tbl + (size_t)i2 * (D_DIM / 4) + lane));
            acc_add(a3, ldcg_f4(tbl + (size_t)i3 * (D_DIM / 4) + lane));
        }
        for (; j < end; j++) {
            const int i0 = indices[j];
            acc_add(a0, ldcg_f4(tbl + (size_t)i0 * (D_DIM / 4) + lane));
        }
    }

    acc_add(a0, a1);
    acc_add(a2, a3);
    acc_add(a0, a2);

    float4* const o =
        reinterpret_cast<float4*>(out + (size_t)b * (T_TABLES * D_DIM) + t * D_DIM);
    o[lane] = a0;
}

extern "C" void kernel_launch(void* const* d_in, const int* in_sizes, int n_in,
                              void* d_out, int out_size) {
    const float* weights = (const float*)d_in[0];
    const int*   indices = (const int*)d_in[1];
    const int*   offsets = (const int*)d_in[2];
    float*       out     = (float*)d_out;

    cudaFuncSetAttribute(tbe_hybrid_kernel,
                         cudaFuncAttributeMaxDynamicSharedMemorySize, SMEM_BYTES);

    const int num_bags = T_TABLES * B_BAGS;        // 65536
    const int blocks   = num_bags / WARPS;          // 8192
    tbe_hybrid_kernel<<<blocks, WARPS * 32, SMEM_BYTES>>>(weights, indices, offsets, out);
}

// round 6
// speedup vs baseline: 1.1603x; 1.0468x over previous
#include <cuda_runtime.h>
#include <stdint.h>

// TBE pooled embedding forward, L=20 fast path, pure LDG gather.
// weights: [T, E, D] fp32; indices: [T*B*L] int32; offsets: [T*B+1] int32
// out: [B, T*D] fp32, pooled bag (t, b) -> out[b, t*D : (t+1)*D]
//
// One warp per bag; lane owns float4 slot of the 512B row -> each row read is
// one coalesced LDG.128 warp transaction. Rows loaded with .cg (L2 only),
// output stored with .cs (streaming) to keep L2 capacity for row dedup.

#define T_TABLES 16
#define E_ROWS   100000
#define D_DIM    128
#define B_BAGS   4096

__device__ __forceinline__ float4 ldcg_f4(const float4* p) {
    float4 v;
    asm volatile("ld.global.cg.v4.f32 {%0,%1,%2,%3}, [%4];"
                 : "=f"(v.x), "=f"(v.y), "=f"(v.z), "=f"(v.w) : "l"(p));
    return v;
}

__device__ __forceinline__ void stcs_f4(float4* p, const float4 v) {
    asm volatile("st.global.cs.v4.f32 [%0], {%1,%2,%3,%4};"
                 :: "l"(p), "f"(v.x), "f"(v.y), "f"(v.z), "f"(v.w) : "memory");
}

__device__ __forceinline__ void acc_add(float4& a, const float4 v) {
    a.x += v.x; a.y += v.y; a.z += v.z; a.w += v.w;
}

__global__ __launch_bounds__(256, 6)
void tbe_forward_kernel(const float* __restrict__ weights,
                        const int* __restrict__ indices,
                        const int* __restrict__ offsets,
                        float* __restrict__ out) {
    const int warp_id = (blockIdx.x * blockDim.x + threadIdx.x) >> 5;
    const int lane    = threadIdx.x & 31;

    const int num_bags = T_TABLES * B_BAGS;
    if (warp_id >= num_bags) return;

    const int t = warp_id / B_BAGS;   // bags are table-major
    const int b = warp_id % B_BAGS;

    const int start = __ldg(offsets + warp_id);
    const int end   = __ldg(offsets + warp_id + 1);
    const int n     = end - start;

    const float4* __restrict__ tbl =
        reinterpret_cast<const float4*>(weights + (size_t)t * E_ROWS * D_DIM);

    float4 a0 = make_float4(0.f, 0.f, 0.f, 0.f);
    float4 a1 = make_float4(0.f, 0.f, 0.f, 0.f);
    float4 a2 = make_float4(0.f, 0.f, 0.f, 0.f);
    float4 a3 = make_float4(0.f, 0.f, 0.f, 0.f);

    if (n == 20 && ((start & 3) == 0)) {
        // 5 vectorized index loads (const path), 20 row gathers.
        const int4* __restrict__ ip = reinterpret_cast<const int4*>(indices + start);
        int idx[20];
        #pragma unroll
        for (int g = 0; g < 5; g++) {
            const int4 q = __ldg(ip + g);
            idx[g * 4 + 0] = q.x;
            idx[g * 4 + 1] = q.y;
            idx[g * 4 + 2] = q.z;
            idx[g * 4 + 3] = q.w;
        }
        float4 v[20];
        #pragma unroll
        for (int k = 0; k < 20; k++)
            v[k] = ldcg_f4(tbl + (size_t)idx[k] * (D_DIM / 4) + lane);
        #pragma unroll
        for (int k = 0; k < 20; k += 4) {
            acc_add(a0, v[k + 0]);
            acc_add(a1, v[k + 1]);
            acc_add(a2, v[k + 2]);
            acc_add(a3, v[k + 3]);
        }
    } else {
        // Generic ragged fallback.
        int j = start;
        const int n4 = start + (n & ~3);
        #pragma unroll 1
        for (; j < n4; j += 4) {
            const int i0 = __ldg(indices + j + 0);
            const int i1 = __ldg(indices + j + 1);
            const int i2 = __ldg(indices + j + 2);
            const int i3 = __ldg(indices + j + 3);
            acc_add(a0, ldcg_f4(tbl + (size_t)i0 * (D_DIM / 4) + lane));
            acc_add(a1, ldcg_f4(tbl + (size_t)i1 * (D_DIM / 4) + lane));
            acc_add(a2, ldcg_f4(tbl + (size_t)i2 * (D_DIM / 4) + lane));
            acc_add(a3, ldcg_f4(tbl + (size_t)i3 * (D_DIM / 4) + lane));
        }
        for (; j < end; j++) {
            const int i0 = __ldg(indices + j);
            acc_add(a0, ldcg_f4(tbl + (size_t)i0 * (D_DIM / 4) + lane));
        }
    }

    acc_add(a0, a1);
    acc_add(a2, a3);
    acc_add(a0, a2);

    float4* const o =
        reinterpret_cast<float4*>(out + (size_t)b * (T_TABLES * D_DIM) + t * D_DIM);
    stcs_f4(o + lane, a0);
}

extern "C" void kernel_launch(void* const* d_in, const int* in_sizes, int n_in,
                              void* d_out, int out_size) {
    const float* weights = (const float*)d_in[0];
    const int*   indices = (const int*)d_in[1];
    const int*   offsets = (const int*)d_in[2];
    float*       out     = (float*)d_out;

    const int num_bags = T_TABLES * B_BAGS;           // 65536 warps
    const int threads  = 256;                          // 8 warps / block
    const int blocks   = (num_bags * 32 + threads - 1) / threads;  // 8192

    tbe_forward_kernel<<<blocks, threads>>>(weights, indices, offsets, out);
}